// round 12
// baseline (speedup 1.0000x reference)
#include <cuda_runtime.h>
#include <cuda_bf16.h>
#include <math.h>
#include <stdint.h>

#define N 8192
#define D 512
#define KSEL 16
#define CCAP 64            // candidate capacity per row
#define FLOORC 64          // histogram floor code (sim >= 32.0)

// ---------------- static device scratch (no runtime allocation) -----------
__device__ __align__(16) __nv_bfloat16 g_xb[(size_t)N * D];        // 8 MB
__device__ __align__(16) uint8_t g_code[(size_t)N * N];            // 64 MB
__device__ int g_cand[N * CCAP];                                   // 2 MB
__device__ int g_cnt[N];

// ======================= helpers ==========================================
__device__ __forceinline__ uint32_t smem_u32(const void* p) {
    uint32_t a;
    asm("{ .reg .u64 t; cvta.to.shared.u64 t, %1; cvt.u32.u64 %0, t; }"
        : "=r"(a) : "l"(p));
    return a;
}
#define CP_ASYNC16(dst, src) \
    asm volatile("cp.async.cg.shared.global [%0], [%1], 16;" :: "r"(dst), "l"(src))
#define CP_ASYNC_COMMIT() asm volatile("cp.async.commit_group;" ::: "memory")
#define CP_ASYNC_WAIT1()  asm volatile("cp.async.wait_group 1;" ::: "memory")
#define CP_ASYNC_WAIT0()  asm volatile("cp.async.wait_group 0;" ::: "memory")

#define LDSM_X4(r0, r1, r2, r3, addr)                                        \
    asm volatile("ldmatrix.sync.aligned.m8n8.x4.shared.b16 {%0,%1,%2,%3}, [%4];" \
                 : "=r"(r0), "=r"(r1), "=r"(r2), "=r"(r3) : "r"(addr))
#define LDSM_X2(r0, r1, addr)                                                \
    asm volatile("ldmatrix.sync.aligned.m8n8.x2.shared.b16 {%0,%1}, [%2];"   \
                 : "=r"(r0), "=r"(r1) : "r"(addr))

__device__ __forceinline__ void mma_bf16(float* c, const unsigned* a, const unsigned* b)
{
    asm volatile(
        "mma.sync.aligned.m16n8k16.row.col.f32.bf16.bf16.f32 "
        "{%0,%1,%2,%3}, {%4,%5,%6,%7}, {%8,%9}, {%0,%1,%2,%3};\n"
        : "+f"(c[0]), "+f"(c[1]), "+f"(c[2]), "+f"(c[3])
        : "r"(a[0]), "r"(a[1]), "r"(a[2]), "r"(a[3]), "r"(b[0]), "r"(b[1]));
}
__device__ __forceinline__ void stcs4(uint4* p, uint4 v) {
    asm volatile("st.global.cs.v4.u32 [%0], {%1,%2,%3,%4};"
                 :: "l"(p), "r"(v.x), "r"(v.y), "r"(v.z), "r"(v.w) : "memory");
}
__device__ __forceinline__ void stcs4f(float4* p, float4 v) {
    asm volatile("st.global.cs.v4.f32 [%0], {%1,%2,%3,%4};"
                 :: "l"(p), "f"(v.x), "f"(v.y), "f"(v.z), "f"(v.w) : "memory");
}
// monotone fp32 -> uint8 code (0.5 resolution over [0, 127.5])
__device__ __forceinline__ uint32_t code_u8(float a) {
    int v = __float2int_rn(a * 2.0f);
    v = v < 0 ? 0 : (v > 255 ? 255 : v);
    return (uint32_t)v;
}

// ---------------------------------------------------------------------------
// Kernel 0: fused pass-through copy + fp32 -> bf16 convert (one read of x)
// ---------------------------------------------------------------------------
__global__ __launch_bounds__(256) void convert_copy_kernel(const float* __restrict__ x,
                                                           float* __restrict__ out_x)
{
    int i4 = blockIdx.x * 256 + threadIdx.x;
    float4 v = ((const float4*)x)[i4];
    ((float4*)out_x)[i4] = v;
    __nv_bfloat162 lo = __floats2bfloat162_rn(v.x, v.y);
    __nv_bfloat162 hi = __floats2bfloat162_rn(v.z, v.w);
    uint2 packed;
    packed.x = *(unsigned*)&lo;
    packed.y = *(unsigned*)&hi;
    ((uint2*)g_xb)[i4] = packed;
}

// ---------------------------------------------------------------------------
// Kernel 1: codes = quantize(Xb * Xb^T), symmetric (bx >= by).
// Lower-triangle CTAs (by > bx) zero the adjacency output instead of exiting:
// the 256 MB zero-fill overlaps the compute-bound MMA phase for free.
// ---------------------------------------------------------------------------
#define BMg 128
#define BNg 128
#define BKg 64
#define BKP 72                          // 144 B rows: conflict-free LDSM
#define STAGES 3
#define A_UNITS (BMg * BKP)
#define B_UNITS (BNg * BKP)
#define STAGE_UNITS (A_UNITS + B_UNITS)
#define PIPE_BYTES (STAGES * STAGE_UNITS * 2)   // 110592
#define TLD 144                         // code-tile row stride
#define SMEM_GEMM PIPE_BYTES
#define NZCTA 2016                      // 64*63/2 lower-triangle CTAs
#define ZCH4 8324                       // uint4 per zeroing CTA (covers 64M floats)

__device__ __forceinline__ void issue_stage(uint32_t sA, uint32_t sB,
                                            int mbase, int nbase, int k0, int tid)
{
#pragma unroll
    for (int i = 0; i < 4; i++) {
        int id  = tid + i * 256;
        int row = id >> 3;
        int c   = id & 7;
        CP_ASYNC16(sA + row * 144 + c * 16,
                   g_xb + (size_t)(mbase + row) * D + k0 + c * 8);
        CP_ASYNC16(sB + row * 144 + c * 16,
                   g_xb + (size_t)(nbase + row) * D + k0 + c * 8);
    }
    CP_ASYNC_COMMIT();
}

__global__ __launch_bounds__(256, 2) void gemm_sym_kernel(float* __restrict__ adj)
{
    const int bx = blockIdx.x;
    const int by = blockIdx.y;

    if (by > bx) {
        // ---- zero-fill a slab of the adjacency (overlaps with MMA CTAs) ----
        const int t = (by * (by - 1)) / 2 + bx;      // 0 .. NZCTA-1
        float4* base = (float4*)adj + (size_t)t * ZCH4;
        const size_t total4 = (size_t)N * N / 4;     // 16M uint4
        const size_t start  = (size_t)t * ZCH4;
        const float4 z = make_float4(0.f, 0.f, 0.f, 0.f);
        for (int u = threadIdx.x; u < ZCH4; u += 256) {
            if (start + u < total4) stcs4f(&base[u], z);
        }
        return;
    }

    extern __shared__ __align__(16) char smem_raw[];
    __nv_bfloat16* smem = (__nv_bfloat16*)smem_raw;
    const uint32_t sb = smem_u32(smem);

    const int tid  = threadIdx.x;
    const int lane = tid & 31;
    const int wid  = tid >> 5;
    const int wm   = wid >> 2;
    const int wn   = wid & 3;
    const int g    = lane >> 2;
    const int t    = lane & 3;

    const int mbase = by * BMg;
    const int nbase = bx * BNg;

    const uint32_t aLaneOff = ((lane & 15) * BKP + (lane >> 4) * 8) * 2 +
                              (wm * 64) * BKP * 2;
    const uint32_t bLaneOff = ((lane & 7) * BKP + ((lane >> 3) & 1) * 8) * 2 +
                              (wn * 32) * BKP * 2;

    float acc[4][4][4];
#pragma unroll
    for (int i = 0; i < 4; i++)
#pragma unroll
        for (int j = 0; j < 4; j++)
#pragma unroll
            for (int q = 0; q < 4; q++) acc[i][j][q] = 0.0f;

#pragma unroll
    for (int s = 0; s < STAGES - 1; s++) {
        uint32_t base = sb + s * STAGE_UNITS * 2;
        issue_stage(base, base + A_UNITS * 2, mbase, nbase, s * BKg, tid);
    }

    const int NT = D / BKg;   // 8
    for (int kt = 0; kt < NT; kt++) {
        CP_ASYNC_WAIT1();
        __syncthreads();

        const int nk = kt + STAGES - 1;
        if (nk < NT) {
            uint32_t base = sb + (nk % STAGES) * STAGE_UNITS * 2;
            issue_stage(base, base + A_UNITS * 2, mbase, nbase, nk * BKg, tid);
        } else {
            CP_ASYNC_COMMIT();   // tail-safe wait_group semantics
        }

        const uint32_t sA = sb + (kt % STAGES) * STAGE_UNITS * 2;
        const uint32_t sB = sA + A_UNITS * 2;
        const uint32_t aBase = sA + aLaneOff;
        const uint32_t bBase = sB + bLaneOff;

#pragma unroll
        for (int s = 0; s < 4; s++) {
            const uint32_t kOff = s * 32;
            unsigned af[4][4], bfr[4][2];
#pragma unroll
            for (int i = 0; i < 4; i++)
                LDSM_X4(af[i][0], af[i][1], af[i][2], af[i][3],
                        aBase + i * (16 * BKP * 2) + kOff);
#pragma unroll
            for (int j = 0; j < 4; j++)
                LDSM_X2(bfr[j][0], bfr[j][1],
                        bBase + j * (8 * BKP * 2) + kOff);
#pragma unroll
            for (int i = 0; i < 4; i++)
#pragma unroll
                for (int j = 0; j < 4; j++)
                    mma_bf16(acc[i][j], af[i], bfr[j]);
        }
    }
    CP_ASYNC_WAIT0();
    __syncthreads();

    // ---- stage uint8 code tile in smem (reuse pipeline smem) ----
    uint8_t* tile = (uint8_t*)smem;
#pragma unroll
    for (int i = 0; i < 4; i++) {
#pragma unroll
        for (int j = 0; j < 4; j++) {
            const int r0 = wm * 64 + i * 16 + g;
            const int c  = wn * 32 + j * 8 + t * 2;
            uint32_t p01 = code_u8(acc[i][j][0]) | (code_u8(acc[i][j][1]) << 8);
            uint32_t p23 = code_u8(acc[i][j][2]) | (code_u8(acc[i][j][3]) << 8);
            *(uint16_t*)&tile[r0 * TLD + c]       = (uint16_t)p01;
            *(uint16_t*)&tile[(r0 + 8) * TLD + c] = (uint16_t)p23;
        }
    }
    __syncthreads();

    // ---- direct write: 128 rows x 128 bytes (streaming) ----
#pragma unroll
    for (int kk = 0; kk < 4; kk++) {
        int u   = tid + kk * 256;
        int row = u >> 3;
        int seg = u & 7;
        stcs4((uint4*)(g_code + (size_t)(mbase + row) * N + nbase + seg * 16),
              *(const uint4*)&tile[row * TLD + seg * 16]);
    }

    // ---- mirror write: transpose bytes ----
    if (bx != by) {
        const int c = tid & 127;
        const int h = tid >> 7;
        uint8_t* dst = g_code + (size_t)(nbase + c) * N + mbase + h * 64;
#pragma unroll
        for (int q = 0; q < 4; q++) {
            uint32_t w[4];
#pragma unroll
            for (int p = 0; p < 4; p++) {
                int rb = h * 64 + q * 16 + p * 4;
                uint32_t b0 = tile[(rb + 0) * TLD + c];
                uint32_t b1 = tile[(rb + 1) * TLD + c];
                uint32_t b2 = tile[(rb + 2) * TLD + c];
                uint32_t b3 = tile[(rb + 3) * TLD + c];
                w[p] = b0 | (b1 << 8) | (b2 << 16) | (b3 << 24);
            }
            stcs4((uint4*)(dst + q * 16), make_uint4(w[0], w[1], w[2], w[3]));
        }
    }
}

// ---------------------------------------------------------------------------
// Kernel 2: candidate selection on uint8 codes (256-bin floored histogram).
// ---------------------------------------------------------------------------
__global__ __launch_bounds__(256) void select_code_kernel()
{
    __shared__ uint32_t rowbuf[2048];   // 8 KB
    __shared__ int hist[256];
    __shared__ int totalHi, sB, sCnt, sIdx;

    const int row  = blockIdx.x;
    const int tid  = threadIdx.x;
    const int lane = tid & 31;
    const int wid  = tid >> 5;

    hist[tid] = 0;
    if (tid == 0) { sIdx = 0; totalHi = 0; }

    const uint4* src = (const uint4*)(g_code + (size_t)row * N);
    ((uint4*)rowbuf)[tid]       = __ldcs(&src[tid]);
    ((uint4*)rowbuf)[tid + 256] = __ldcs(&src[tid + 256]);
    __syncthreads();

    // pass 1: floored histogram
    int myc = 0;
#pragma unroll
    for (int i = 0; i < 8; i++) {
        uint32_t w = rowbuf[tid + i * 256];
#pragma unroll
        for (int b = 0; b < 4; b++) {
            uint32_t v = (w >> (8 * b)) & 255u;
            if (v >= FLOORC) { atomicAdd(&hist[v], 1); myc++; }
        }
    }
#pragma unroll
    for (int off = 16; off > 0; off >>= 1)
        myc += __shfl_down_sync(0xffffffff, myc, off);
    if (lane == 0) atomicAdd(&totalHi, myc);
    __syncthreads();

    // fallback: full histogram (correctness guard)
    if (totalHi < 32) {
        hist[tid] = 0;
        __syncthreads();
#pragma unroll
        for (int i = 0; i < 8; i++) {
            uint32_t w = rowbuf[tid + i * 256];
#pragma unroll
            for (int b = 0; b < 4; b++)
                atomicAdd(&hist[(w >> (8 * b)) & 255u], 1);
        }
        __syncthreads();
    }

    // boundary scan in warp 0
    if (wid == 0) {
        const int b0 = lane * 8;
        int csum = 0;
#pragma unroll
        for (int k = 0; k < 8; k++) csum += hist[b0 + k];
        int v = csum;
#pragma unroll
        for (int off = 1; off < 32; off <<= 1) {
            int n = __shfl_down_sync(0xffffffff, v, off);
            if (lane + off < 32) v += n;
        }
        int Snext = v - csum;
        if (v >= 32 && Snext < 32) {
            int cum = Snext;
            int b = b0 + 7;
            for (; b >= b0; b--) {
                cum += hist[b];
                if (cum >= 32) break;
            }
            sB = b;
            sCnt = cum;
        }
    }
    __syncthreads();
    const uint32_t B = (uint32_t)sB;

    // pass 2: collect all codes >= B
#pragma unroll
    for (int i = 0; i < 8; i++) {
        const int u = tid + i * 256;
        uint32_t w = rowbuf[u];
#pragma unroll
        for (int b = 0; b < 4; b++) {
            uint32_t v = (w >> (8 * b)) & 255u;
            if (v >= B) {
                int slot = atomicAdd(&sIdx, 1);
                if (slot < CCAP) g_cand[row * CCAP + slot] = 4 * u + b;
            }
        }
    }
    __syncthreads();
    if (tid == 0) g_cnt[row] = (sCnt < CCAP) ? sCnt : CCAP;
}

// ---------------------------------------------------------------------------
// Kernel 3: exact fp32 rescore (float4 gathers), top-16, scatter.
// Zero-fill already done by the GEMM's idle CTAs.
// ---------------------------------------------------------------------------
__global__ __launch_bounds__(256) void rescore_kernel(const float* __restrict__ x,
                                                      float* __restrict__ adj)
{
    __shared__ __align__(16) float xr[D];
    __shared__ float cv[CCAP];
    __shared__ int   ci[CCAP];

    const int row  = blockIdx.x;
    const int tid  = threadIdx.x;
    const int lane = tid & 31;
    const int wid  = tid >> 5;

    const int cnt = g_cnt[row];

    if (tid < CCAP) { cv[tid] = -INFINITY; ci[tid] = -1; }
    {
        const float4* xs = (const float4*)(x + (size_t)row * D);
        if (tid < D / 4) ((float4*)xr)[tid] = xs[tid];
    }
    __syncthreads();

    const float4* xr4 = (const float4*)xr;
#pragma unroll
    for (int j = 0; j < CCAP / 8; j++) {
        const int c = wid + j * 8;
        if (c < cnt) {
            const int col = g_cand[row * CCAP + c];
            const float4* xc = (const float4*)(x + (size_t)col * D);
            float sum = 0.0f;
#pragma unroll
            for (int k = 0; k < D / 128; k++) {
                float4 a = xr4[lane + k * 32];
                float4 b = xc[lane + k * 32];
                sum = fmaf(a.x, b.x, sum);
                sum = fmaf(a.y, b.y, sum);
                sum = fmaf(a.z, b.z, sum);
                sum = fmaf(a.w, b.w, sum);
            }
#pragma unroll
            for (int off = 16; off > 0; off >>= 1)
                sum += __shfl_down_sync(0xffffffff, sum, off);
            if (lane == 0) { cv[c] = sum; ci[c] = col; }
        }
    }
    __syncthreads();

    // rank (value desc, col asc on tie) and scatter top-16
    if (tid < cnt) {
        const float v   = cv[tid];
        const int   col = ci[tid];
        int rank = 0;
#pragma unroll
        for (int j2 = 0; j2 < CCAP; j2++) {
            float vj = cv[j2];
            int   cj = ci[j2];
            rank += (vj > v) || (vj == v && cj < col);
        }
        if (rank < KSEL) adj[(size_t)row * N + col] = v;
    }
}

// ---------------------------------------------------------------------------
// Launch
// ---------------------------------------------------------------------------
extern "C" void kernel_launch(void* const* d_in, const int* in_sizes, int n_in,
                              void* d_out, int out_size)
{
    const float* x = (const float*)d_in[0];
    float* out = (float*)d_out;

    float* out_x   = out;
    float* out_adj = out + (size_t)N * D;

    // fused copy + convert
    convert_copy_kernel<<<(N * D) / 1024, 256>>>(x, out_x);

    cudaFuncSetAttribute(gemm_sym_kernel,
                         cudaFuncAttributeMaxDynamicSharedMemorySize, SMEM_GEMM);
    dim3 grid(N / BNg, N / BMg);
    gemm_sym_kernel<<<grid, 256, SMEM_GEMM>>>(out_adj);

    select_code_kernel<<<N, 256>>>();

    rescore_kernel<<<N, 256>>>(x, out_adj);
}

// round 13
// speedup vs baseline: 1.1535x; 1.1535x over previous
#include <cuda_runtime.h>
#include <cuda_bf16.h>
#include <math.h>
#include <stdint.h>

#define N 8192
#define D 512
#define KSEL 16
#define CCAP 64            // candidate capacity per row
#define FLOORC 64          // histogram floor code (sim >= 32.0)

// ---------------- static device scratch (no runtime allocation) -----------
__device__ __align__(16) __nv_bfloat16 g_xb[(size_t)N * D];        // 8 MB
__device__ __align__(16) uint8_t g_code[(size_t)N * N];            // 64 MB

// ======================= helpers ==========================================
__device__ __forceinline__ uint32_t smem_u32(const void* p) {
    uint32_t a;
    asm("{ .reg .u64 t; cvta.to.shared.u64 t, %1; cvt.u32.u64 %0, t; }"
        : "=r"(a) : "l"(p));
    return a;
}
#define CP_ASYNC16(dst, src) \
    asm volatile("cp.async.cg.shared.global [%0], [%1], 16;" :: "r"(dst), "l"(src))
#define CP_ASYNC_COMMIT() asm volatile("cp.async.commit_group;" ::: "memory")
#define CP_ASYNC_WAIT1()  asm volatile("cp.async.wait_group 1;" ::: "memory")
#define CP_ASYNC_WAIT0()  asm volatile("cp.async.wait_group 0;" ::: "memory")

#define LDSM_X4(r0, r1, r2, r3, addr)                                        \
    asm volatile("ldmatrix.sync.aligned.m8n8.x4.shared.b16 {%0,%1,%2,%3}, [%4];" \
                 : "=r"(r0), "=r"(r1), "=r"(r2), "=r"(r3) : "r"(addr))
#define LDSM_X2(r0, r1, addr)                                                \
    asm volatile("ldmatrix.sync.aligned.m8n8.x2.shared.b16 {%0,%1}, [%2];"   \
                 : "=r"(r0), "=r"(r1) : "r"(addr))

__device__ __forceinline__ void mma_bf16(float* c, const unsigned* a, const unsigned* b)
{
    asm volatile(
        "mma.sync.aligned.m16n8k16.row.col.f32.bf16.bf16.f32 "
        "{%0,%1,%2,%3}, {%4,%5,%6,%7}, {%8,%9}, {%0,%1,%2,%3};\n"
        : "+f"(c[0]), "+f"(c[1]), "+f"(c[2]), "+f"(c[3])
        : "r"(a[0]), "r"(a[1]), "r"(a[2]), "r"(a[3]), "r"(b[0]), "r"(b[1]));
}
__device__ __forceinline__ void stcs4(uint4* p, uint4 v) {
    asm volatile("st.global.cs.v4.u32 [%0], {%1,%2,%3,%4};"
                 :: "l"(p), "r"(v.x), "r"(v.y), "r"(v.z), "r"(v.w) : "memory");
}
__device__ __forceinline__ void stcs4f(float4* p, float4 v) {
    asm volatile("st.global.cs.v4.f32 [%0], {%1,%2,%3,%4};"
                 :: "l"(p), "f"(v.x), "f"(v.y), "f"(v.z), "f"(v.w) : "memory");
}
// monotone fp32 -> uint8 code (0.5 resolution over [0, 127.5])
__device__ __forceinline__ uint32_t code_u8(float a) {
    int v = __float2int_rn(a * 2.0f);
    v = v < 0 ? 0 : (v > 255 ? 255 : v);
    return (uint32_t)v;
}

// ---------------------------------------------------------------------------
// Kernel 0: fused pass-through copy + fp32 -> bf16 convert (one read of x)
// ---------------------------------------------------------------------------
__global__ __launch_bounds__(256) void convert_copy_kernel(const float* __restrict__ x,
                                                           float* __restrict__ out_x)
{
    int i4 = blockIdx.x * 256 + threadIdx.x;
    float4 v = ((const float4*)x)[i4];
    ((float4*)out_x)[i4] = v;
    __nv_bfloat162 lo = __floats2bfloat162_rn(v.x, v.y);
    __nv_bfloat162 hi = __floats2bfloat162_rn(v.z, v.w);
    uint2 packed;
    packed.x = *(unsigned*)&lo;
    packed.y = *(unsigned*)&hi;
    ((uint2*)g_xb)[i4] = packed;
}

// ---------------------------------------------------------------------------
// Kernel 1: codes = quantize(Xb * Xb^T), symmetric (bx >= by).
// Each MMA CTA ALSO zeroes a slab of the adjacency, interleaved into the
// k-loop (fire-and-forget streaming stores riding the GEMM's idle DRAM).
// ---------------------------------------------------------------------------
#define BMg 128
#define BNg 128
#define BKg 64
#define BKP 72                          // 144 B rows: conflict-free LDSM
#define STAGES 3
#define A_UNITS (BMg * BKP)
#define B_UNITS (BNg * BKP)
#define STAGE_UNITS (A_UNITS + B_UNITS)
#define PIPE_BYTES (STAGES * STAGE_UNITS * 2)   // 110592
#define TLD 144                         // code-tile row stride
#define SMEM_GEMM PIPE_BYTES
#define NUPPER 2080                     // 64*65/2 upper-triangle CTAs
#define ZCH4 8067                       // float4 per MMA CTA (covers 16M float4)
#define ZPI  1009                       // float4 per CTA per k-iteration

__device__ __forceinline__ void issue_stage(uint32_t sA, uint32_t sB,
                                            int mbase, int nbase, int k0, int tid)
{
#pragma unroll
    for (int i = 0; i < 4; i++) {
        int id  = tid + i * 256;
        int row = id >> 3;
        int c   = id & 7;
        CP_ASYNC16(sA + row * 144 + c * 16,
                   g_xb + (size_t)(mbase + row) * D + k0 + c * 8);
        CP_ASYNC16(sB + row * 144 + c * 16,
                   g_xb + (size_t)(nbase + row) * D + k0 + c * 8);
    }
    CP_ASYNC_COMMIT();
}

__global__ __launch_bounds__(256, 2) void gemm_sym_kernel(float* __restrict__ adj)
{
    const int bx = blockIdx.x;
    const int by = blockIdx.y;
    if (by > bx) return;

    extern __shared__ __align__(16) char smem_raw[];
    __nv_bfloat16* smem = (__nv_bfloat16*)smem_raw;
    const uint32_t sb = smem_u32(smem);

    const int tid  = threadIdx.x;
    const int lane = tid & 31;
    const int wid  = tid >> 5;
    const int wm   = wid >> 2;
    const int wn   = wid & 3;
    const int g    = lane >> 2;
    const int t    = lane & 3;

    const int mbase = by * BMg;
    const int nbase = bx * BNg;

    // zero-fill slab for this upper-triangle CTA
    const int ztile = by * 64 - (by * (by - 1)) / 2 + (bx - by);  // 0..2079
    const size_t zstart = (size_t)ztile * ZCH4;
    const size_t ztotal = (size_t)N * N / 4;
    float4* zbase = (float4*)adj + zstart;
    const float4 zv = make_float4(0.f, 0.f, 0.f, 0.f);

    const uint32_t aLaneOff = ((lane & 15) * BKP + (lane >> 4) * 8) * 2 +
                              (wm * 64) * BKP * 2;
    const uint32_t bLaneOff = ((lane & 7) * BKP + ((lane >> 3) & 1) * 8) * 2 +
                              (wn * 32) * BKP * 2;

    float acc[4][4][4];
#pragma unroll
    for (int i = 0; i < 4; i++)
#pragma unroll
        for (int j = 0; j < 4; j++)
#pragma unroll
            for (int q = 0; q < 4; q++) acc[i][j][q] = 0.0f;

#pragma unroll
    for (int s = 0; s < STAGES - 1; s++) {
        uint32_t base = sb + s * STAGE_UNITS * 2;
        issue_stage(base, base + A_UNITS * 2, mbase, nbase, s * BKg, tid);
    }

    const int NT = D / BKg;   // 8
    for (int kt = 0; kt < NT; kt++) {
        CP_ASYNC_WAIT1();
        __syncthreads();

        const int nk = kt + STAGES - 1;
        if (nk < NT) {
            uint32_t base = sb + (nk % STAGES) * STAGE_UNITS * 2;
            issue_stage(base, base + A_UNITS * 2, mbase, nbase, nk * BKg, tid);
        } else {
            CP_ASYNC_COMMIT();   // tail-safe wait_group semantics
        }

        // interleaved adjacency zero-fill: ~4 streaming stores per thread
#pragma unroll
        for (int i = 0; i < 4; i++) {
            int u = kt * ZPI + i * 256 + tid;
            if (u < ZCH4 && zstart + u < ztotal) stcs4f(&zbase[u], zv);
        }

        const uint32_t sA = sb + (kt % STAGES) * STAGE_UNITS * 2;
        const uint32_t sB = sA + A_UNITS * 2;
        const uint32_t aBase = sA + aLaneOff;
        const uint32_t bBase = sB + bLaneOff;

#pragma unroll
        for (int s = 0; s < 4; s++) {
            const uint32_t kOff = s * 32;
            unsigned af[4][4], bfr[4][2];
#pragma unroll
            for (int i = 0; i < 4; i++)
                LDSM_X4(af[i][0], af[i][1], af[i][2], af[i][3],
                        aBase + i * (16 * BKP * 2) + kOff);
#pragma unroll
            for (int j = 0; j < 4; j++)
                LDSM_X2(bfr[j][0], bfr[j][1],
                        bBase + j * (8 * BKP * 2) + kOff);
#pragma unroll
            for (int i = 0; i < 4; i++)
#pragma unroll
                for (int j = 0; j < 4; j++)
                    mma_bf16(acc[i][j], af[i], bfr[j]);
        }
    }
    CP_ASYNC_WAIT0();
    __syncthreads();

    // ---- stage uint8 code tile in smem (reuse pipeline smem) ----
    uint8_t* tile = (uint8_t*)smem;
#pragma unroll
    for (int i = 0; i < 4; i++) {
#pragma unroll
        for (int j = 0; j < 4; j++) {
            const int r0 = wm * 64 + i * 16 + g;
            const int c  = wn * 32 + j * 8 + t * 2;
            uint32_t p01 = code_u8(acc[i][j][0]) | (code_u8(acc[i][j][1]) << 8);
            uint32_t p23 = code_u8(acc[i][j][2]) | (code_u8(acc[i][j][3]) << 8);
            *(uint16_t*)&tile[r0 * TLD + c]       = (uint16_t)p01;
            *(uint16_t*)&tile[(r0 + 8) * TLD + c] = (uint16_t)p23;
        }
    }
    __syncthreads();

    // ---- direct write: 128 rows x 128 bytes (streaming) ----
#pragma unroll
    for (int kk = 0; kk < 4; kk++) {
        int u   = tid + kk * 256;
        int row = u >> 3;
        int seg = u & 7;
        stcs4((uint4*)(g_code + (size_t)(mbase + row) * N + nbase + seg * 16),
              *(const uint4*)&tile[row * TLD + seg * 16]);
    }

    // ---- mirror write: transpose bytes ----
    if (bx != by) {
        const int c = tid & 127;
        const int h = tid >> 7;
        uint8_t* dst = g_code + (size_t)(nbase + c) * N + mbase + h * 64;
#pragma unroll
        for (int q = 0; q < 4; q++) {
            uint32_t w[4];
#pragma unroll
            for (int p = 0; p < 4; p++) {
                int rb = h * 64 + q * 16 + p * 4;
                uint32_t b0 = tile[(rb + 0) * TLD + c];
                uint32_t b1 = tile[(rb + 1) * TLD + c];
                uint32_t b2 = tile[(rb + 2) * TLD + c];
                uint32_t b3 = tile[(rb + 3) * TLD + c];
                w[p] = b0 | (b1 << 8) | (b2 << 16) | (b3 << 24);
            }
            stcs4((uint4*)(dst + q * 16), make_uint4(w[0], w[1], w[2], w[3]));
        }
    }
}

// ---------------------------------------------------------------------------
// Kernel 2: fused select (256-bin floored histogram) + exact fp32 rescore +
// top-16 scatter. Candidates never leave shared memory.
// ---------------------------------------------------------------------------
__global__ __launch_bounds__(256) void select_rescore_kernel(
    const float* __restrict__ x, float* __restrict__ adj)
{
    __shared__ uint32_t rowbuf[2048];       // 8 KB codes
    __shared__ int hist[256];
    __shared__ __align__(16) float xr[D];   // 2 KB
    __shared__ int   scand[CCAP];
    __shared__ float cv[CCAP];
    __shared__ int   sci[CCAP];
    __shared__ int totalHi, sB, sCnt, sIdx;

    const int row  = blockIdx.x;
    const int tid  = threadIdx.x;
    const int lane = tid & 31;
    const int wid  = tid >> 5;

    hist[tid] = 0;
    if (tid < CCAP) { cv[tid] = -INFINITY; sci[tid] = -1; }
    if (tid == 0) { sIdx = 0; totalHi = 0; }

    const uint4* src = (const uint4*)(g_code + (size_t)row * N);
    ((uint4*)rowbuf)[tid]       = __ldcs(&src[tid]);
    ((uint4*)rowbuf)[tid + 256] = __ldcs(&src[tid + 256]);
    if (tid < D / 4)
        ((float4*)xr)[tid] = ((const float4*)(x + (size_t)row * D))[tid];
    __syncthreads();

    // pass 1: floored histogram
    int myc = 0;
#pragma unroll
    for (int i = 0; i < 8; i++) {
        uint32_t w = rowbuf[tid + i * 256];
#pragma unroll
        for (int b = 0; b < 4; b++) {
            uint32_t v = (w >> (8 * b)) & 255u;
            if (v >= FLOORC) { atomicAdd(&hist[v], 1); myc++; }
        }
    }
#pragma unroll
    for (int off = 16; off > 0; off >>= 1)
        myc += __shfl_down_sync(0xffffffff, myc, off);
    if (lane == 0) atomicAdd(&totalHi, myc);
    __syncthreads();

    // fallback: full histogram (correctness guard; not taken for this data)
    if (totalHi < 32) {
        hist[tid] = 0;
        __syncthreads();
#pragma unroll
        for (int i = 0; i < 8; i++) {
            uint32_t w = rowbuf[tid + i * 256];
#pragma unroll
            for (int b = 0; b < 4; b++)
                atomicAdd(&hist[(w >> (8 * b)) & 255u], 1);
        }
        __syncthreads();
    }

    // boundary scan in warp 0
    if (wid == 0) {
        const int b0 = lane * 8;
        int csum = 0;
#pragma unroll
        for (int k = 0; k < 8; k++) csum += hist[b0 + k];
        int v = csum;
#pragma unroll
        for (int off = 1; off < 32; off <<= 1) {
            int n = __shfl_down_sync(0xffffffff, v, off);
            if (lane + off < 32) v += n;
        }
        int Snext = v - csum;
        if (v >= 32 && Snext < 32) {
            int cum = Snext;
            int b = b0 + 7;
            for (; b >= b0; b--) {
                cum += hist[b];
                if (cum >= 32) break;
            }
            sB = b;
            sCnt = cum;
        }
    }
    __syncthreads();
    const uint32_t B = (uint32_t)sB;

    // pass 2: collect candidate columns into smem
#pragma unroll
    for (int i = 0; i < 8; i++) {
        const int u = tid + i * 256;
        uint32_t w = rowbuf[u];
#pragma unroll
        for (int b = 0; b < 4; b++) {
            uint32_t v = (w >> (8 * b)) & 255u;
            if (v >= B) {
                int slot = atomicAdd(&sIdx, 1);
                if (slot < CCAP) scand[slot] = 4 * u + b;
            }
        }
    }
    __syncthreads();
    const int cnt = (sCnt < CCAP) ? sCnt : CCAP;

    // exact fp32 rescore of candidates (float4 gathers from L2-resident x)
    const float4* xr4 = (const float4*)xr;
#pragma unroll
    for (int j = 0; j < CCAP / 8; j++) {
        const int c = wid + j * 8;
        if (c < cnt) {
            const int col = scand[c];
            const float4* xc = (const float4*)(x + (size_t)col * D);
            float sum = 0.0f;
#pragma unroll
            for (int k = 0; k < D / 128; k++) {
                float4 a = xr4[lane + k * 32];
                float4 b = xc[lane + k * 32];
                sum = fmaf(a.x, b.x, sum);
                sum = fmaf(a.y, b.y, sum);
                sum = fmaf(a.z, b.z, sum);
                sum = fmaf(a.w, b.w, sum);
            }
#pragma unroll
            for (int off = 16; off > 0; off >>= 1)
                sum += __shfl_down_sync(0xffffffff, sum, off);
            if (lane == 0) { cv[c] = sum; sci[c] = col; }
        }
    }
    __syncthreads();

    // rank (value desc, col asc on tie) and scatter top-16
    if (tid < cnt) {
        const float v   = cv[tid];
        const int   col = sci[tid];
        int rank = 0;
#pragma unroll
        for (int j2 = 0; j2 < CCAP; j2++) {
            float vj = cv[j2];
            int   cj = sci[j2];
            rank += (vj > v) || (vj == v && cj < col);
        }
        if (rank < KSEL) adj[(size_t)row * N + col] = v;
    }
}

// ---------------------------------------------------------------------------
// Launch
// ---------------------------------------------------------------------------
extern "C" void kernel_launch(void* const* d_in, const int* in_sizes, int n_in,
                              void* d_out, int out_size)
{
    const float* x = (const float*)d_in[0];
    float* out = (float*)d_out;

    float* out_x   = out;
    float* out_adj = out + (size_t)N * D;

    convert_copy_kernel<<<(N * D) / 1024, 256>>>(x, out_x);

    cudaFuncSetAttribute(gemm_sym_kernel,
                         cudaFuncAttributeMaxDynamicSharedMemorySize, SMEM_GEMM);
    dim3 grid(N / BNg, N / BMg);
    gemm_sym_kernel<<<grid, 256, SMEM_GEMM>>>(out_adj);

    select_rescore_kernel<<<N, 256>>>(x, out_adj);
}